// round 16
// baseline (speedup 1.0000x reference)
#include <cuda_runtime.h>
#include <cuda_fp16.h>
#include <math.h>
#include <stdint.h>

// ---------------------------------------------------------------------------
// GatedDeltaNet, B=2,S=1024,H=2048,HV=32,HK=16,DK=DV=128,KW=4.
// 2-term fp16 GEMMs (C = (Ah+Al)@Bh^T), unsplit qkv GEMM (R14 shapes),
// fused conv_qk on main + conv_v on s2 (parallel), time-chunked scalar
// recurrence, 3-stream pipelined schedule.
// ---------------------------------------------------------------------------
#define BB   2
#define SS   1024
#define TT   (BB*SS)
#define HH   2048
#define HV   32
#define HK   16
#define DK   128
#define DV   128
#define KW   4
#define KEY_DIM  (HK*DK)             // 2048
#define VAL_DIM  (HV*DV)             // 4096
#define CONV_DIM (2*KEY_DIM+VAL_DIM) // 8192
#define SHALF (SS/2)                 // 512

// ------------------------- scratch (device globals) ------------------------
__device__ float g_qkv_pre[TT * CONV_DIM];
__device__ float g_v      [TT * VAL_DIM];        // conv+silu'd v (compact)
__device__ float g_z      [TT * VAL_DIM];
__device__ float g_qn     [TT * HV * DK];
__device__ float g_kn     [TT * HV * DK];
__device__ float g_g      [TT * HV];
__device__ float g_beta   [TT * HV];
__device__ float g_core   [TT * HV * DV];
__device__ float g_state  [BB * HV * DK * DV];   // rec chunk state carry (4MB)
// fp16 operands
__device__ __half g_xh[TT * HH],      g_xl[TT * HH];
__device__ __half g_WqkvT[CONV_DIM * HH];
__device__ __half g_WzT[VAL_DIM * HH];
__device__ __half g_WoutT[HH * VAL_DIM];
__device__ __half g_nrm_h[TT * VAL_DIM], g_nrm_l[TT * VAL_DIM];

// ---------------------------------------------------------------------------
// helpers
// ---------------------------------------------------------------------------
__device__ __forceinline__ void hsplit(float v, __half& h, __half& l) {
    h = __float2half_rn(v);
    l = __float2half_rn(v - __half2float(h));
}

#define SWZ64(o) ((o) ^ (((o) >> 3) & 0x30))

#define CP16(dst, src)                                                         \
    asm volatile("cp.async.cg.shared.global [%0], [%1], 16;" ::                \
                 "r"(dst), "l"(src))

#define LDSM4(r0, r1, r2, r3, a)                                               \
    asm volatile("ldmatrix.sync.aligned.m8n8.x4.shared.b16 {%0,%1,%2,%3},[%4];"\
                 : "=r"(r0), "=r"(r1), "=r"(r2), "=r"(r3) : "r"(a))

#define MMA_FP16(d, a, b)                                                      \
    asm volatile("mma.sync.aligned.m16n8k16.row.col.f32.f16.f16.f32 "          \
                 "{%0,%1,%2,%3},{%4,%5,%6,%7},{%8,%9},{%0,%1,%2,%3};"          \
                 : "+f"((d)[0]), "+f"((d)[1]), "+f"((d)[2]), "+f"((d)[3])      \
                 : "r"((a)[0]), "r"((a)[1]), "r"((a)[2]), "r"((a)[3]),         \
                   "r"((b)[0]), "r"((b)[1]))

// ---------------------------------------------------------------------------
// 2-term fp16 GEMM: C[M,N] = (Ah+Al)[M,K] @ (Bh[N,K])^T
// CTA 128x128, 256 threads (8 warps of 64x32), BK=32, 3-stage cp.async,
// SW64-swizzled 64B rows, ONE __syncthreads per k-chunk.
// ---------------------------------------------------------------------------
#define BKE   32
#define TILEB 8192
#define OFF_AH 0
#define OFF_AL (1*TILEB)
#define OFF_BH (2*TILEB)
#define STG    (3*TILEB)            // 24576 bytes per stage
#define NSTG   3
#define GEMM_SMEM (NSTG*STG)        // 73728

__device__ __forceinline__ void load_stage(
    const __half* __restrict__ Ah, const __half* __restrict__ Al,
    const __half* __restrict__ Bh,
    int bm, int bn, int K, int kc, uint32_t sbase, int tid)
{
#pragma unroll
    for (int i = 0; i < 2; i++) {
        int c    = tid + 256 * i;
        int row  = c >> 2;
        int k16  = c & 3;
        uint32_t off = SWZ64((uint32_t)(row * 64 + k16 * 16));
        size_t gofs = (size_t)kc * BKE + k16 * 8;
        CP16(sbase + OFF_AH + off, Ah + (size_t)(bm + row) * K + gofs);
        CP16(sbase + OFF_AL + off, Al + (size_t)(bm + row) * K + gofs);
        CP16(sbase + OFF_BH + off, Bh + (size_t)(bn + row) * K + gofs);
    }
    asm volatile("cp.async.commit_group;" ::: "memory");
}

__global__ __launch_bounds__(256) void gemm_fp16_2t(
    const __half* __restrict__ Ah, const __half* __restrict__ Al,
    const __half* __restrict__ Bh,
    float* __restrict__ C, int M, int N, int K)
{
    extern __shared__ __align__(128) char smem[];
    const uint32_t sb = (uint32_t)__cvta_generic_to_shared(smem);
    const int tid  = threadIdx.x;
    const int lane = tid & 31;
    const int wid  = tid >> 5;
    const int wm   = (wid >> 2) * 64;
    const int wn   = (wid & 3) * 32;
    const int bm = blockIdx.y * 128;
    const int bn = blockIdx.x * 128;

    float acc[4][4][4];
#pragma unroll
    for (int mf = 0; mf < 4; mf++)
#pragma unroll
        for (int nf = 0; nf < 4; nf++)
#pragma unroll
            for (int i = 0; i < 4; i++) acc[mf][nf][i] = 0.f;

    const int NC = K / BKE;
    load_stage(Ah, Al, Bh, bm, bn, K, 0, sb + 0 * STG, tid);
    load_stage(Ah, Al, Bh, bm, bn, K, 1, sb + 1 * STG, tid);

    const int lrow = lane & 15;
    const int lkb  = (lane >> 4) * 16;

    int buf = 0, nxt = 2;
    for (int c = 0; c < NC; c++) {
        if (c + 1 < NC) asm volatile("cp.async.wait_group 1;" ::: "memory");
        else            asm volatile("cp.async.wait_group 0;" ::: "memory");
        __syncthreads();

        if (c + 2 < NC)
            load_stage(Ah, Al, Bh, bm, bn, K, c + 2, sb + nxt * STG, tid);

        const uint32_t base = sb + buf * STG;
#pragma unroll
        for (int ks = 0; ks < 2; ks++) {
            const int kb = ks * 32 + lkb;
            uint32_t ah[4][4], al[4][4], bh[4][2];
#pragma unroll
            for (int mf = 0; mf < 4; mf++) {
                uint32_t off = SWZ64((uint32_t)((wm + mf * 16 + lrow) * 64 + kb));
                LDSM4(ah[mf][0], ah[mf][1], ah[mf][2], ah[mf][3], base + OFF_AH + off);
                LDSM4(al[mf][0], al[mf][1], al[mf][2], al[mf][3], base + OFF_AL + off);
            }
#pragma unroll
            for (int nf2 = 0; nf2 < 2; nf2++) {
                uint32_t off = SWZ64((uint32_t)((wn + nf2 * 16 + lrow) * 64 + kb));
                uint32_t t0, t1, t2, t3;
                LDSM4(t0, t1, t2, t3, base + OFF_BH + off);
                bh[nf2 * 2 + 0][0] = t0; bh[nf2 * 2 + 0][1] = t2;
                bh[nf2 * 2 + 1][0] = t1; bh[nf2 * 2 + 1][1] = t3;
            }
#pragma unroll
            for (int mf = 0; mf < 4; mf++)
#pragma unroll
                for (int nf = 0; nf < 4; nf++) {
                    MMA_FP16(acc[mf][nf], ah[mf], bh[nf]);
                    MMA_FP16(acc[mf][nf], al[mf], bh[nf]);
                }
        }

        buf = (buf + 1 == NSTG) ? 0 : buf + 1;
        nxt = (nxt + 1 == NSTG) ? 0 : nxt + 1;
    }

    const int g   = lane >> 2;
    const int tig = lane & 3;
#pragma unroll
    for (int mf = 0; mf < 4; mf++)
#pragma unroll
        for (int nf = 0; nf < 4; nf++) {
            int r  = bm + wm + mf * 16 + g;
            int cc = bn + wn + nf * 8 + tig * 2;
            *reinterpret_cast<float2*>(&C[(size_t)r * N + cc]) =
                make_float2(acc[mf][nf][0], acc[mf][nf][1]);
            *reinterpret_cast<float2*>(&C[(size_t)(r + 8) * N + cc]) =
                make_float2(acc[mf][nf][2], acc[mf][nf][3]);
        }
}

// ---------------------------------------------------------------------------
// split fp32 -> fp16 hi/lo (row-major, elementwise)
// ---------------------------------------------------------------------------
__global__ __launch_bounds__(256) void split_fp16(
    const float4* __restrict__ in, __half* __restrict__ h,
    __half* __restrict__ l, int n4)
{
    int i = blockIdx.x * 256 + threadIdx.x;
    if (i >= n4) return;
    float4 v = in[i];
    __half h0, l0, h1, l1, h2, l2, h3, l3;
    hsplit(v.x, h0, l0); hsplit(v.y, h1, l1);
    hsplit(v.z, h2, l2); hsplit(v.w, h3, l3);
    __half2* hp = (__half2*)(h + (size_t)i * 4);
    __half2* lp = (__half2*)(l + (size_t)i * 4);
    hp[0] = __half2(h0, h1); hp[1] = __half2(h2, h3);
    lp[0] = __half2(l0, l1); lp[1] = __half2(l2, l3);
}

// ---------------------------------------------------------------------------
// transpose + convert: W[K][N] fp32 -> T[N][K] fp16 (single, rn)
// ---------------------------------------------------------------------------
__global__ __launch_bounds__(256) void cvt_fp16_T(
    const float* __restrict__ W, __half* __restrict__ Th, int K, int N)
{
    __shared__ float tile[32][33];
    const int bx = blockIdx.x * 32;   // N
    const int by = blockIdx.y * 32;   // K
    const int tx = threadIdx.x & 31, ty = threadIdx.x >> 5;
#pragma unroll
    for (int i = 0; i < 32; i += 8)
        tile[ty + i][tx] = W[(size_t)(by + ty + i) * N + bx + tx];
    __syncthreads();
#pragma unroll
    for (int i = 0; i < 32; i += 8) {
        size_t o = (size_t)(bx + ty + i) * K + by + tx;
        Th[o] = __float2half_rn(tile[tx][ty + i]);
    }
}

// ---------------------------------------------------------------------------
// Fused causal conv + SiLU + l2norm for q/k, writing head-repeated qn/kn.
// One CTA per (t, hk), 128 threads.
// ---------------------------------------------------------------------------
__global__ __launch_bounds__(128) void conv_qk(
    const float* __restrict__ pre, const float* __restrict__ cw,
    const float* __restrict__ cb, float* __restrict__ qn,
    float* __restrict__ kn)
{
    const int blk = blockIdx.x;
    const int t = blk / HK, hk = blk % HK;
    const int dk = threadIdx.x;
    const int b = t / SS, s = t % SS;
    const int chq = hk * DK + dk;
    const int chk = KEY_DIM + hk * DK + dk;

    float aq = cb[chq], ak = cb[chk];
#pragma unroll
    for (int j = 0; j < KW; j++) {
        int sp = s - (KW - 1) + j;
        if (sp >= 0) {
            size_t row = (size_t)(b * SS + sp) * CONV_DIM;
            aq += pre[row + chq] * cw[chq * KW + j];
            ak += pre[row + chk] * cw[chk * KW + j];
        }
    }
    float qv = aq / (1.f + expf(-aq));
    float kv = ak / (1.f + expf(-ak));

    __shared__ float s1[128], s2[128];
    s1[dk] = qv * qv;
    s2[dk] = kv * kv;
    __syncthreads();
#pragma unroll
    for (int off = 64; off > 0; off >>= 1) {
        if (dk < off) { s1[dk] += s1[dk + off]; s2[dk] += s2[dk + off]; }
        __syncthreads();
    }
    __shared__ float rq, rk;
    if (dk == 0) {
        rq = rsqrtf(s1[0] + 1e-6f);
        rk = rsqrtf(s2[0] + 1e-6f);
    }
    __syncthreads();

    float qo = qv * rq * 0.08838834764831845f;   // * DK^-0.5
    float ko = kv * rk;
    int h0 = hk * 2;
    size_t base0 = ((size_t)t * HV + h0) * DK + dk;
    size_t base1 = ((size_t)t * HV + h0 + 1) * DK + dk;
    qn[base0] = qo; qn[base1] = qo;
    kn[base0] = ko; kn[base1] = ko;
}

// ---------------------------------------------------------------------------
// Causal conv + SiLU for the v channels -> compact g_v[T][VAL_DIM]
// ---------------------------------------------------------------------------
__global__ __launch_bounds__(256) void conv_v(
    const float* __restrict__ pre, const float* __restrict__ cw,
    const float* __restrict__ cb, float* __restrict__ vout)
{
    int c  = blockIdx.x * 256 + threadIdx.x;   // 0..VAL_DIM-1
    int ch = 2 * KEY_DIM + c;
    int t  = blockIdx.y;
    int b = t / SS, s = t % SS;
    float acc = cb[ch];
#pragma unroll
    for (int j = 0; j < KW; j++) {
        int sp = s - (KW - 1) + j;
        if (sp >= 0)
            acc += pre[(size_t)(b * SS + sp) * CONV_DIM + ch] * cw[ch * KW + j];
    }
    vout[(size_t)t * VAL_DIM + c] = acc / (1.f + expf(-acc));
}

// ---------------------------------------------------------------------------
// beta / g projections
// ---------------------------------------------------------------------------
__global__ __launch_bounds__(256) void proj_gb(
    const float* __restrict__ x, const float* __restrict__ Wb,
    const float* __restrict__ Wa, const float* __restrict__ dt_bias,
    const float* __restrict__ A_log, float* __restrict__ gout,
    float* __restrict__ bout)
{
    int t = blockIdx.x;
    __shared__ float xs[HH];
    const float4* xr = reinterpret_cast<const float4*>(x + (size_t)t * HH);
    float4* xs4 = reinterpret_cast<float4*>(xs);
    for (int i = threadIdx.x; i < HH / 4; i += 256) xs4[i] = xr[i];
    __syncthreads();

    int out  = threadIdx.x >> 2;
    int part = threadIdx.x & 3;
    const float* W = (out < 32) ? Wb : Wa;
    int col = out & 31;

    float acc = 0.f;
    int k0 = part * (HH / 4);
#pragma unroll 8
    for (int k = k0; k < k0 + HH / 4; k++)
        acc += xs[k] * W[k * HV + col];

    acc += __shfl_xor_sync(0xffffffffu, acc, 1);
    acc += __shfl_xor_sync(0xffffffffu, acc, 2);

    if (part == 0) {
        if (out < 32) {
            bout[t * HV + col] = 1.f / (1.f + expf(-acc));
        } else {
            float v = acc + dt_bias[col];
            float sp = (v > 20.f) ? v : log1pf(expf(v));
            gout[t * HV + col] = -expf(A_log[col]) * sp;
        }
    }
}

// ---------------------------------------------------------------------------
// Gated delta-rule recurrence, 128 CTAs (2 per chain, dv-halved), smem-reduce.
// Time-chunked: [s_begin, s_end) with exact fp32 state carry via g_state.
// v read from compact vbuf[T][VAL_DIM].
// ---------------------------------------------------------------------------
__global__ __launch_bounds__(128) void recurrence(
    const float* __restrict__ qn, const float* __restrict__ kn,
    const float* __restrict__ vbuf, const float* __restrict__ gg,
    const float* __restrict__ bb, float* __restrict__ core,
    float* __restrict__ state, int s_begin, int s_end,
    int load_st, int store_st)
{
    const int cid   = blockIdx.x;          // 0..127
    const int chain = cid >> 1;            // b*HV + h
    const int dvh   = (cid & 1) * 64;
    const int b = chain / HV, h = chain % HV;
    const int tid = threadIdx.x;
    const int dvl = tid & 63;
    const int dkh = (tid >> 6) * 64;
    const int dv  = dvh + dvl;
    const size_t stbase = (size_t)chain * (DK * DV);

    float st[64];
    if (load_st) {
#pragma unroll
        for (int i = 0; i < 64; i++)
            st[i] = state[stbase + (size_t)(dkh + i) * DV + dv];
    } else {
#pragma unroll
        for (int i = 0; i < 64; i++) st[i] = 0.f;
    }

    __shared__ float ks[2][DK], qs[2][DK], red1[128], red2[128];

    const int t0 = b * SS + s_begin;
    ks[s_begin & 1][tid] = kn[((size_t)t0 * HV + h) * DK + tid];
    qs[s_begin & 1][tid] = qn[((size_t)t0 * HV + h) * DK + tid];
    float gv = gg[t0 * HV + h];
    float bv = bb[t0 * HV + h];
    float vv = vbuf[(size_t)t0 * VAL_DIM + h * DV + dv];
    __syncthreads();

    for (int s = s_begin; s < s_end; s++) {
        const int cur = s & 1;
        const int t = b * SS + s;

        float knx = 0.f, qnx = 0.f, gnx = 0.f, bnx = 0.f, vnx = 0.f;
        if (s + 1 < s_end) {
            int tn = t + 1;
            knx = kn[((size_t)tn * HV + h) * DK + tid];
            qnx = qn[((size_t)tn * HV + h) * DK + tid];
            gnx = gg[tn * HV + h];
            bnx = bb[tn * HV + h];
            vnx = vbuf[(size_t)tn * VAL_DIM + h * DV + dv];
        }

        const float dec = expf(gv);

        float m0 = 0.f, m1 = 0.f, m2 = 0.f, m3 = 0.f;
#pragma unroll
        for (int i = 0; i < 64; i += 4) {
            float4 kk = *reinterpret_cast<const float4*>(&ks[cur][dkh + i]);
            st[i + 0] *= dec; m0 += kk.x * st[i + 0];
            st[i + 1] *= dec; m1 += kk.y * st[i + 1];
            st[i + 2] *= dec; m2 += kk.z * st[i + 2];
            st[i + 3] *= dec; m3 += kk.w * st[i + 3];
        }
        red1[tid] = (m0 + m1) + (m2 + m3);
        __syncthreads();
        const float mem = red1[tid] + red1[tid ^ 64];
        const float delta = (vv - mem) * bv;

        float o0 = 0.f, o1 = 0.f, o2 = 0.f, o3 = 0.f;
#pragma unroll
        for (int i = 0; i < 64; i += 4) {
            float4 kk = *reinterpret_cast<const float4*>(&ks[cur][dkh + i]);
            float4 qq = *reinterpret_cast<const float4*>(&qs[cur][dkh + i]);
            st[i + 0] += kk.x * delta; o0 += qq.x * st[i + 0];
            st[i + 1] += kk.y * delta; o1 += qq.y * st[i + 1];
            st[i + 2] += kk.z * delta; o2 += qq.z * st[i + 2];
            st[i + 3] += kk.w * delta; o3 += qq.w * st[i + 3];
        }
        red2[tid] = (o0 + o1) + (o2 + o3);

        if (s + 1 < s_end) {
            ks[cur ^ 1][tid] = knx;
            qs[cur ^ 1][tid] = qnx;
        }
        __syncthreads();
        if (dkh == 0)
            core[((size_t)t * HV + h) * DV + dv] = red2[tid] + red2[tid ^ 64];

        gv = gnx; bv = bnx; vv = vnx;
    }

    if (store_st) {
#pragma unroll
        for (int i = 0; i < 64; i++)
            state[stbase + (size_t)(dkh + i) * DV + dv] = st[i];
    }
}

// ---------------------------------------------------------------------------
// gated RMSNorm -> fp16 hi/lo; t_off selects the token slice
// ---------------------------------------------------------------------------
__global__ __launch_bounds__(128) void gated_norm(
    const float* __restrict__ core, const float* __restrict__ z,
    const float* __restrict__ nw, __half* __restrict__ nh,
    __half* __restrict__ nl, int t_off)
{
    int bh = blockIdx.x + t_off * HV;
    int dv = threadIdx.x;
    size_t idx = (size_t)bh * DV + dv;

    float c  = core[idx];
    float zv = z[idx];
    float gz = c * (zv / (1.f + expf(-zv)));

    __shared__ float red[128];
    red[dv] = gz * gz;
    __syncthreads();
#pragma unroll
    for (int off = 64; off > 0; off >>= 1) {
        if (dv < off) red[dv] += red[dv + off];
        __syncthreads();
    }
    __shared__ float rs;
    if (dv == 0) rs = rsqrtf(red[0] * (1.f / DV) + 1e-6f);
    __syncthreads();

    __half h, l;
    hsplit(gz * rs * nw[dv], h, l);
    nh[idx] = h; nl[idx] = l;
}

// ---------------------------------------------------------------------------
// launch — 3-stream pipelined overlap (graph-capturable event fork/join)
// ---------------------------------------------------------------------------
extern "C" void kernel_launch(void* const* d_in, const int* in_sizes, int n_in,
                              void* d_out, int out_size)
{
    const float* x       = (const float*)d_in[0];
    const float* Wqkv    = (const float*)d_in[1];
    const float* Wz      = (const float*)d_in[2];
    const float* Wb      = (const float*)d_in[3];
    const float* Wa      = (const float*)d_in[4];
    const float* conv_w  = (const float*)d_in[5];
    const float* conv_b  = (const float*)d_in[6];
    const float* dt_bias = (const float*)d_in[7];
    const float* A_log   = (const float*)d_in[8];
    const float* norm_w  = (const float*)d_in[9];
    const float* Wout    = (const float*)d_in[10];
    float* out = (float*)d_out;

    float *qkv_pre, *vbuf, *z, *qn, *kn, *gbuf, *bbuf, *core, *state;
    __half *xh, *xl, *WqT, *WzT, *WoT, *nh, *nl;
    cudaGetSymbolAddress((void**)&qkv_pre, g_qkv_pre);
    cudaGetSymbolAddress((void**)&vbuf,    g_v);
    cudaGetSymbolAddress((void**)&z,       g_z);
    cudaGetSymbolAddress((void**)&qn,      g_qn);
    cudaGetSymbolAddress((void**)&kn,      g_kn);
    cudaGetSymbolAddress((void**)&gbuf,    g_g);
    cudaGetSymbolAddress((void**)&bbuf,    g_beta);
    cudaGetSymbolAddress((void**)&core,    g_core);
    cudaGetSymbolAddress((void**)&state,   g_state);
    cudaGetSymbolAddress((void**)&xh,      g_xh);
    cudaGetSymbolAddress((void**)&xl,      g_xl);
    cudaGetSymbolAddress((void**)&WqT,     g_WqkvT);
    cudaGetSymbolAddress((void**)&WzT,     g_WzT);
    cudaGetSymbolAddress((void**)&WoT,     g_WoutT);
    cudaGetSymbolAddress((void**)&nh,      g_nrm_h);
    cudaGetSymbolAddress((void**)&nl,      g_nrm_l);

    static cudaStream_t s1 = nullptr, s2 = nullptr;
    static cudaEvent_t ev_root, ev_prep, ev_qkv, ev_convv, ev_z0, ev_z1,
                       ev_rec0, ev_out1;
    if (!s1) {
        cudaStreamCreateWithFlags(&s1, cudaStreamNonBlocking);
        cudaStreamCreateWithFlags(&s2, cudaStreamNonBlocking);
        cudaEventCreateWithFlags(&ev_root, cudaEventDisableTiming);
        cudaEventCreateWithFlags(&ev_prep, cudaEventDisableTiming);
        cudaEventCreateWithFlags(&ev_qkv,  cudaEventDisableTiming);
        cudaEventCreateWithFlags(&ev_convv, cudaEventDisableTiming);
        cudaEventCreateWithFlags(&ev_z0,   cudaEventDisableTiming);
        cudaEventCreateWithFlags(&ev_z1,   cudaEventDisableTiming);
        cudaEventCreateWithFlags(&ev_rec0, cudaEventDisableTiming);
        cudaEventCreateWithFlags(&ev_out1, cudaEventDisableTiming);
        cudaFuncSetAttribute(gemm_fp16_2t,
            cudaFuncAttributeMaxDynamicSharedMemorySize, GEMM_SMEM);
    }

    // fork s1/s2 off main
    cudaEventRecord(ev_root, 0);
    cudaStreamWaitEvent(s1, ev_root, 0);
    cudaStreamWaitEvent(s2, ev_root, 0);

    // main: x split + Wqkv convert -> qkv GEMM (unsplit, R14 shape)
    split_fp16<<<(TT * HH / 4 + 255) / 256, 256>>>(
        (const float4*)x, xh, xl, TT * HH / 4);
    cvt_fp16_T<<<dim3(CONV_DIM / 32, HH / 32), 256>>>(Wqkv, WqT, HH, CONV_DIM);

    // s1: Wz/Wout converts + proj_gb (overlap qkv GEMM)
    cvt_fp16_T<<<dim3(VAL_DIM / 32, HH / 32), 256, 0, s1>>>(Wz, WzT, HH, VAL_DIM);
    cvt_fp16_T<<<dim3(HH / 32, VAL_DIM / 32), 256, 0, s1>>>(Wout, WoT, VAL_DIM, HH);
    proj_gb<<<TT, 256, 0, s1>>>(x, Wb, Wa, dt_bias, A_log, gbuf, bbuf);
    cudaEventRecord(ev_prep, s1);

    // main: qkv GEMM
    gemm_fp16_2t<<<dim3(CONV_DIM / 128, TT / 128), 256, GEMM_SMEM>>>(
        xh, xl, WqT, qkv_pre, TT, CONV_DIM, HH);
    cudaEventRecord(ev_qkv, 0);

    // s2: conv_v runs concurrently with main's conv_qk
    cudaStreamWaitEvent(s2, ev_qkv, 0);
    conv_v<<<dim3(VAL_DIM / 256, TT), 256, 0, s2>>>(
        qkv_pre, conv_w, conv_b, vbuf);
    cudaEventRecord(ev_convv, s2);

    // s1: z GEMM chunked by token rows: chunk0 = tokens [0,512)+[1024,1536)
    cudaStreamWaitEvent(s1, ev_qkv, 0);
    gemm_fp16_2t<<<dim3(VAL_DIM / 128, SHALF / 128), 256, GEMM_SMEM, s1>>>(
        xh, xl, WzT, z, SHALF, VAL_DIM, HH);
    gemm_fp16_2t<<<dim3(VAL_DIM / 128, SHALF / 128), 256, GEMM_SMEM, s1>>>(
        xh + (size_t)SS * HH, xl + (size_t)SS * HH, WzT,
        z + (size_t)SS * VAL_DIM, SHALF, VAL_DIM, HH);
    cudaEventRecord(ev_z0, s1);
    gemm_fp16_2t<<<dim3(VAL_DIM / 128, SHALF / 128), 256, GEMM_SMEM, s1>>>(
        xh + (size_t)SHALF * HH, xl + (size_t)SHALF * HH, WzT,
        z + (size_t)SHALF * VAL_DIM, SHALF, VAL_DIM, HH);
    gemm_fp16_2t<<<dim3(VAL_DIM / 128, SHALF / 128), 256, GEMM_SMEM, s1>>>(
        xh + (size_t)(SS + SHALF) * HH, xl + (size_t)(SS + SHALF) * HH,
        WzT, z + (size_t)(SS + SHALF) * VAL_DIM, SHALF, VAL_DIM, HH);
    cudaEventRecord(ev_z1, s1);

    // main: fused conv_qk, then rec chunk 0 (needs conv_v + proj_gb too)
    conv_qk<<<TT * HK, 128>>>(qkv_pre, conv_w, conv_b, qn, kn);
    cudaStreamWaitEvent(0, ev_prep, 0);
    cudaStreamWaitEvent(0, ev_convv, 0);
    recurrence<<<BB * HV * 2, 128>>>(qn, kn, vbuf, gbuf, bbuf, core,
                                     state, 0, SHALF, 0, 1);
    cudaEventRecord(ev_rec0, 0);

    // s2: norm + out-GEMM for chunk-0 token slices (overlaps rec chunk 1)
    cudaStreamWaitEvent(s2, ev_z0, 0);
    cudaStreamWaitEvent(s2, ev_rec0, 0);
    gated_norm<<<SHALF * HV, 128, 0, s2>>>(core, z, norm_w, nh, nl, 0);
    gated_norm<<<SHALF * HV, 128, 0, s2>>>(core, z, norm_w, nh, nl, SS);
    gemm_fp16_2t<<<dim3(HH / 128, SHALF / 128), 256, GEMM_SMEM, s2>>>(
        nh, nl, WoT, out, SHALF, HH, VAL_DIM);
    gemm_fp16_2t<<<dim3(HH / 128, SHALF / 128), 256, GEMM_SMEM, s2>>>(
        nh + (size_t)SS * VAL_DIM, nl + (size_t)SS * VAL_DIM, WoT,
        out + (size_t)SS * HH, SHALF, HH, VAL_DIM);
    cudaEventRecord(ev_out1, s2);

    // main: rec chunk 1, then norm+out for chunk-1 slices
    recurrence<<<BB * HV * 2, 128>>>(qn, kn, vbuf, gbuf, bbuf, core,
                                     state, SHALF, SS, 1, 0);
    cudaStreamWaitEvent(0, ev_z1, 0);
    gated_norm<<<SHALF * HV, 128>>>(core, z, norm_w, nh, nl, SHALF);
    gated_norm<<<SHALF * HV, 128>>>(core, z, norm_w, nh, nl, SS + SHALF);
    gemm_fp16_2t<<<dim3(HH / 128, SHALF / 128), 256, GEMM_SMEM>>>(
        nh + (size_t)SHALF * VAL_DIM, nl + (size_t)SHALF * VAL_DIM,
        WoT, out + (size_t)SHALF * HH, SHALF, HH, VAL_DIM);
    gemm_fp16_2t<<<dim3(HH / 128, SHALF / 128), 256, GEMM_SMEM>>>(
        nh + (size_t)(SS + SHALF) * VAL_DIM, nl + (size_t)(SS + SHALF) * VAL_DIM,
        WoT, out + (size_t)(SS + SHALF) * HH, SHALF, HH, VAL_DIM);

    // join s2 back into main before capture ends
    cudaStreamWaitEvent(0, ev_out1, 0);
}

// round 17
// speedup vs baseline: 1.0350x; 1.0350x over previous
#include <cuda_runtime.h>
#include <cuda_fp16.h>
#include <math.h>
#include <stdint.h>

// ---------------------------------------------------------------------------
// GatedDeltaNet, B=2,S=1024,H=2048,HV=32,HK=16,DK=DV=128,KW=4.
// R14 pipeline (best: 1794us) with the z projection demoted to a 1-term
// plain fp16 GEMM (z only feeds the silu gate; its error is independent and
// adds in quadrature). qkv/out stay 2-term (A = fp16 hi+lo).
// ---------------------------------------------------------------------------
#define BB   2
#define SS   1024
#define TT   (BB*SS)
#define HH   2048
#define HV   32
#define HK   16
#define DK   128
#define DV   128
#define KW   4
#define KEY_DIM  (HK*DK)             // 2048
#define VAL_DIM  (HV*DV)             // 4096
#define CONV_DIM (2*KEY_DIM+VAL_DIM) // 8192
#define SHALF (SS/2)                 // 512

// ------------------------- scratch (device globals) ------------------------
__device__ float g_qkv_pre[TT * CONV_DIM];
__device__ float g_mixed  [TT * CONV_DIM];
__device__ float g_z      [TT * VAL_DIM];
__device__ float g_qn     [TT * HV * DK];
__device__ float g_kn     [TT * HV * DK];
__device__ float g_g      [TT * HV];
__device__ float g_beta   [TT * HV];
__device__ float g_core   [TT * HV * DV];
__device__ float g_state  [BB * HV * DK * DV];
// fp16 operands
__device__ __half g_xh[TT * HH],      g_xl[TT * HH];
__device__ __half g_WqkvT[CONV_DIM * HH];
__device__ __half g_WzT[VAL_DIM * HH];
__device__ __half g_WoutT[HH * VAL_DIM];
__device__ __half g_nrm_h[TT * VAL_DIM], g_nrm_l[TT * VAL_DIM];

// ---------------------------------------------------------------------------
// helpers
// ---------------------------------------------------------------------------
__device__ __forceinline__ void hsplit(float v, __half& h, __half& l) {
    h = __float2half_rn(v);
    l = __float2half_rn(v - __half2float(h));
}

#define SWZ64(o) ((o) ^ (((o) >> 3) & 0x30))

#define CP16(dst, src)                                                         \
    asm volatile("cp.async.cg.shared.global [%0], [%1], 16;" ::                \
                 "r"(dst), "l"(src))

#define LDSM4(r0, r1, r2, r3, a)                                               \
    asm volatile("ldmatrix.sync.aligned.m8n8.x4.shared.b16 {%0,%1,%2,%3},[%4];"\
                 : "=r"(r0), "=r"(r1), "=r"(r2), "=r"(r3) : "r"(a))

#define MMA_FP16(d, a, b)                                                      \
    asm volatile("mma.sync.aligned.m16n8k16.row.col.f32.f16.f16.f32 "          \
                 "{%0,%1,%2,%3},{%4,%5,%6,%7},{%8,%9},{%0,%1,%2,%3};"          \
                 : "+f"((d)[0]), "+f"((d)[1]), "+f"((d)[2]), "+f"((d)[3])      \
                 : "r"((a)[0]), "r"((a)[1]), "r"((a)[2]), "r"((a)[3]),         \
                   "r"((b)[0]), "r"((b)[1]))

// ---------------------------------------------------------------------------
// 2-term fp16 GEMM: C[M,N] = (Ah+Al)[M,K] @ (Bh[N,K])^T
// CTA 128x128, 256 threads (8 warps of 64x32), BK=32, 3-stage cp.async,
// SW64-swizzled 64B rows, ONE __syncthreads per k-chunk.
// ---------------------------------------------------------------------------
#define BKE   32
#define TILEB 8192
#define OFF_AH 0
#define OFF_AL (1*TILEB)
#define OFF_BH (2*TILEB)
#define STG    (3*TILEB)            // 24576 bytes per stage
#define NSTG   3
#define GEMM_SMEM (NSTG*STG)        // 73728
// 1-term variant
#define OFF1_B (1*TILEB)
#define STG1   (2*TILEB)            // 16384 bytes per stage
#define GEMM1_SMEM (NSTG*STG1)      // 49152

__device__ __forceinline__ void load_stage(
    const __half* __restrict__ Ah, const __half* __restrict__ Al,
    const __half* __restrict__ Bh,
    int bm, int bn, int K, int kc, uint32_t sbase, int tid)
{
#pragma unroll
    for (int i = 0; i < 2; i++) {
        int c    = tid + 256 * i;
        int row  = c >> 2;
        int k16  = c & 3;
        uint32_t off = SWZ64((uint32_t)(row * 64 + k16 * 16));
        size_t gofs = (size_t)kc * BKE + k16 * 8;
        CP16(sbase + OFF_AH + off, Ah + (size_t)(bm + row) * K + gofs);
        CP16(sbase + OFF_AL + off, Al + (size_t)(bm + row) * K + gofs);
        CP16(sbase + OFF_BH + off, Bh + (size_t)(bn + row) * K + gofs);
    }
    asm volatile("cp.async.commit_group;" ::: "memory");
}

__global__ __launch_bounds__(256) void gemm_fp16_2t(
    const __half* __restrict__ Ah, const __half* __restrict__ Al,
    const __half* __restrict__ Bh,
    float* __restrict__ C, int M, int N, int K)
{
    extern __shared__ __align__(128) char smem[];
    const uint32_t sb = (uint32_t)__cvta_generic_to_shared(smem);
    const int tid  = threadIdx.x;
    const int lane = tid & 31;
    const int wid  = tid >> 5;
    const int wm   = (wid >> 2) * 64;
    const int wn   = (wid & 3) * 32;
    const int bm = blockIdx.y * 128;
    const int bn = blockIdx.x * 128;

    float acc[4][4][4];
#pragma unroll
    for (int mf = 0; mf < 4; mf++)
#pragma unroll
        for (int nf = 0; nf < 4; nf++)
#pragma unroll
            for (int i = 0; i < 4; i++) acc[mf][nf][i] = 0.f;

    const int NC = K / BKE;
    load_stage(Ah, Al, Bh, bm, bn, K, 0, sb + 0 * STG, tid);
    load_stage(Ah, Al, Bh, bm, bn, K, 1, sb + 1 * STG, tid);

    const int lrow = lane & 15;
    const int lkb  = (lane >> 4) * 16;

    int buf = 0, nxt = 2;
    for (int c = 0; c < NC; c++) {
        if (c + 1 < NC) asm volatile("cp.async.wait_group 1;" ::: "memory");
        else            asm volatile("cp.async.wait_group 0;" ::: "memory");
        __syncthreads();

        if (c + 2 < NC)
            load_stage(Ah, Al, Bh, bm, bn, K, c + 2, sb + nxt * STG, tid);

        const uint32_t base = sb + buf * STG;
#pragma unroll
        for (int ks = 0; ks < 2; ks++) {
            const int kb = ks * 32 + lkb;
            uint32_t ah[4][4], al[4][4], bh[4][2];
#pragma unroll
            for (int mf = 0; mf < 4; mf++) {
                uint32_t off = SWZ64((uint32_t)((wm + mf * 16 + lrow) * 64 + kb));
                LDSM4(ah[mf][0], ah[mf][1], ah[mf][2], ah[mf][3], base + OFF_AH + off);
                LDSM4(al[mf][0], al[mf][1], al[mf][2], al[mf][3], base + OFF_AL + off);
            }
#pragma unroll
            for (int nf2 = 0; nf2 < 2; nf2++) {
                uint32_t off = SWZ64((uint32_t)((wn + nf2 * 16 + lrow) * 64 + kb));
                uint32_t t0, t1, t2, t3;
                LDSM4(t0, t1, t2, t3, base + OFF_BH + off);
                bh[nf2 * 2 + 0][0] = t0; bh[nf2 * 2 + 0][1] = t2;
                bh[nf2 * 2 + 1][0] = t1; bh[nf2 * 2 + 1][1] = t3;
            }
#pragma unroll
            for (int mf = 0; mf < 4; mf++)
#pragma unroll
                for (int nf = 0; nf < 4; nf++) {
                    MMA_FP16(acc[mf][nf], ah[mf], bh[nf]);
                    MMA_FP16(acc[mf][nf], al[mf], bh[nf]);
                }
        }

        buf = (buf + 1 == NSTG) ? 0 : buf + 1;
        nxt = (nxt + 1 == NSTG) ? 0 : nxt + 1;
    }

    const int g   = lane >> 2;
    const int tig = lane & 3;
#pragma unroll
    for (int mf = 0; mf < 4; mf++)
#pragma unroll
        for (int nf = 0; nf < 4; nf++) {
            int r  = bm + wm + mf * 16 + g;
            int cc = bn + wn + nf * 8 + tig * 2;
            *reinterpret_cast<float2*>(&C[(size_t)r * N + cc]) =
                make_float2(acc[mf][nf][0], acc[mf][nf][1]);
            *reinterpret_cast<float2*>(&C[(size_t)(r + 8) * N + cc]) =
                make_float2(acc[mf][nf][2], acc[mf][nf][3]);
        }
}

// ---------------------------------------------------------------------------
// 1-term fp16 GEMM: C[M,N] = Ah[M,K] @ (Bh[N,K])^T   (z projection only)
// ---------------------------------------------------------------------------
__device__ __forceinline__ void load_stage1(
    const __half* __restrict__ Ah, const __half* __restrict__ Bh,
    int bm, int bn, int K, int kc, uint32_t sbase, int tid)
{
#pragma unroll
    for (int i = 0; i < 2; i++) {
        int c    = tid + 256 * i;
        int row  = c >> 2;
        int k16  = c & 3;
        uint32_t off = SWZ64((uint32_t)(row * 64 + k16 * 16));
        size_t gofs = (size_t)kc * BKE + k16 * 8;
        CP16(sbase + off,          Ah + (size_t)(bm + row) * K + gofs);
        CP16(sbase + OFF1_B + off, Bh + (size_t)(bn + row) * K + gofs);
    }
    asm volatile("cp.async.commit_group;" ::: "memory");
}

__global__ __launch_bounds__(256) void gemm_fp16_1t(
    const __half* __restrict__ Ah, const __half* __restrict__ Bh,
    float* __restrict__ C, int M, int N, int K)
{
    extern __shared__ __align__(128) char smem[];
    const uint32_t sb = (uint32_t)__cvta_generic_to_shared(smem);
    const int tid  = threadIdx.x;
    const int lane = tid & 31;
    const int wid  = tid >> 5;
    const int wm   = (wid >> 2) * 64;
    const int wn   = (wid & 3) * 32;
    const int bm = blockIdx.y * 128;
    const int bn = blockIdx.x * 128;

    float acc[4][4][4];
#pragma unroll
    for (int mf = 0; mf < 4; mf++)
#pragma unroll
        for (int nf = 0; nf < 4; nf++)
#pragma unroll
            for (int i = 0; i < 4; i++) acc[mf][nf][i] = 0.f;

    const int NC = K / BKE;
    load_stage1(Ah, Bh, bm, bn, K, 0, sb + 0 * STG1, tid);
    load_stage1(Ah, Bh, bm, bn, K, 1, sb + 1 * STG1, tid);

    const int lrow = lane & 15;
    const int lkb  = (lane >> 4) * 16;

    int buf = 0, nxt = 2;
    for (int c = 0; c < NC; c++) {
        if (c + 1 < NC) asm volatile("cp.async.wait_group 1;" ::: "memory");
        else            asm volatile("cp.async.wait_group 0;" ::: "memory");
        __syncthreads();

        if (c + 2 < NC)
            load_stage1(Ah, Bh, bm, bn, K, c + 2, sb + nxt * STG1, tid);

        const uint32_t base = sb + buf * STG1;
#pragma unroll
        for (int ks = 0; ks < 2; ks++) {
            const int kb = ks * 32 + lkb;
            uint32_t ah[4][4], bh[4][2];
#pragma unroll
            for (int mf = 0; mf < 4; mf++) {
                uint32_t off = SWZ64((uint32_t)((wm + mf * 16 + lrow) * 64 + kb));
                LDSM4(ah[mf][0], ah[mf][1], ah[mf][2], ah[mf][3], base + off);
            }
#pragma unroll
            for (int nf2 = 0; nf2 < 2; nf2++) {
                uint32_t off = SWZ64((uint32_t)((wn + nf2 * 16 + lrow) * 64 + kb));
                uint32_t t0, t1, t2, t3;
                LDSM4(t0, t1, t2, t3, base + OFF1_B + off);
                bh[nf2 * 2 + 0][0] = t0; bh[nf2 * 2 + 0][1] = t2;
                bh[nf2 * 2 + 1][0] = t1; bh[nf2 * 2 + 1][1] = t3;
            }
#pragma unroll
            for (int mf = 0; mf < 4; mf++)
#pragma unroll
                for (int nf = 0; nf < 4; nf++)
                    MMA_FP16(acc[mf][nf], ah[mf], bh[nf]);
        }

        buf = (buf + 1 == NSTG) ? 0 : buf + 1;
        nxt = (nxt + 1 == NSTG) ? 0 : nxt + 1;
    }

    const int g   = lane >> 2;
    const int tig = lane & 3;
#pragma unroll
    for (int mf = 0; mf < 4; mf++)
#pragma unroll
        for (int nf = 0; nf < 4; nf++) {
            int r  = bm + wm + mf * 16 + g;
            int cc = bn + wn + nf * 8 + tig * 2;
            *reinterpret_cast<float2*>(&C[(size_t)r * N + cc]) =
                make_float2(acc[mf][nf][0], acc[mf][nf][1]);
            *reinterpret_cast<float2*>(&C[(size_t)(r + 8) * N + cc]) =
                make_float2(acc[mf][nf][2], acc[mf][nf][3]);
        }
}

// ---------------------------------------------------------------------------
// split fp32 -> fp16 hi/lo (row-major, elementwise)
// ---------------------------------------------------------------------------
__global__ __launch_bounds__(256) void split_fp16(
    const float4* __restrict__ in, __half* __restrict__ h,
    __half* __restrict__ l, int n4)
{
    int i = blockIdx.x * 256 + threadIdx.x;
    if (i >= n4) return;
    float4 v = in[i];
    __half h0, l0, h1, l1, h2, l2, h3, l3;
    hsplit(v.x, h0, l0); hsplit(v.y, h1, l1);
    hsplit(v.z, h2, l2); hsplit(v.w, h3, l3);
    __half2* hp = (__half2*)(h + (size_t)i * 4);
    __half2* lp = (__half2*)(l + (size_t)i * 4);
    hp[0] = __half2(h0, h1); hp[1] = __half2(h2, h3);
    lp[0] = __half2(l0, l1); lp[1] = __half2(l2, l3);
}

// ---------------------------------------------------------------------------
// transpose + convert: W[K][N] fp32 -> T[N][K] fp16 (single, rn)
// ---------------------------------------------------------------------------
__global__ __launch_bounds__(256) void cvt_fp16_T(
    const float* __restrict__ W, __half* __restrict__ Th, int K, int N)
{
    __shared__ float tile[32][33];
    const int bx = blockIdx.x * 32;   // N
    const int by = blockIdx.y * 32;   // K
    const int tx = threadIdx.x & 31, ty = threadIdx.x >> 5;
#pragma unroll
    for (int i = 0; i < 32; i += 8)
        tile[ty + i][tx] = W[(size_t)(by + ty + i) * N + bx + tx];
    __syncthreads();
#pragma unroll
    for (int i = 0; i < 32; i += 8) {
        size_t o = (size_t)(bx + ty + i) * K + by + tx;
        Th[o] = __float2half_rn(tile[tx][ty + i]);
    }
}

// ---------------------------------------------------------------------------
// Causal depthwise conv (KW=4) + SiLU
// ---------------------------------------------------------------------------
__global__ __launch_bounds__(256) void conv_silu(
    const float* __restrict__ pre, const float* __restrict__ cw,
    const float* __restrict__ cb, float* __restrict__ out)
{
    int c = blockIdx.x * 256 + threadIdx.x;
    int t = blockIdx.y;
    int b = t / SS, s = t % SS;
    float acc = cb[c];
#pragma unroll
    for (int j = 0; j < KW; j++) {
        int sp = s - (KW - 1) + j;
        if (sp >= 0)
            acc += pre[(size_t)(b * SS + sp) * CONV_DIM + c] * cw[c * KW + j];
    }
    out[(size_t)t * CONV_DIM + c] = acc / (1.f + expf(-acc));
}

// ---------------------------------------------------------------------------
// beta / g projections
// ---------------------------------------------------------------------------
__global__ __launch_bounds__(256) void proj_gb(
    const float* __restrict__ x, const float* __restrict__ Wb,
    const float* __restrict__ Wa, const float* __restrict__ dt_bias,
    const float* __restrict__ A_log, float* __restrict__ gout,
    float* __restrict__ bout)
{
    int t = blockIdx.x;
    __shared__ float xs[HH];
    const float4* xr = reinterpret_cast<const float4*>(x + (size_t)t * HH);
    float4* xs4 = reinterpret_cast<float4*>(xs);
    for (int i = threadIdx.x; i < HH / 4; i += 256) xs4[i] = xr[i];
    __syncthreads();

    int out  = threadIdx.x >> 2;
    int part = threadIdx.x & 3;
    const float* W = (out < 32) ? Wb : Wa;
    int col = out & 31;

    float acc = 0.f;
    int k0 = part * (HH / 4);
#pragma unroll 8
    for (int k = k0; k < k0 + HH / 4; k++)
        acc += xs[k] * W[k * HV + col];

    acc += __shfl_xor_sync(0xffffffffu, acc, 1);
    acc += __shfl_xor_sync(0xffffffffu, acc, 2);

    if (part == 0) {
        if (out < 32) {
            bout[t * HV + col] = 1.f / (1.f + expf(-acc));
        } else {
            float v = acc + dt_bias[col];
            float sp = (v > 20.f) ? v : log1pf(expf(v));
            gout[t * HV + col] = -expf(A_log[col]) * sp;
        }
    }
}

// ---------------------------------------------------------------------------
// q/k l2-normalization + head-repeat
// ---------------------------------------------------------------------------
__global__ __launch_bounds__(128) void qk_prep(
    const float* __restrict__ mixed, float* __restrict__ qn,
    float* __restrict__ kn)
{
    int blk = blockIdx.x;
    int t = blk / HK, hk = blk % HK;
    int dk = threadIdx.x;

    float qv = mixed[(size_t)t * CONV_DIM + hk * DK + dk];
    float kv = mixed[(size_t)t * CONV_DIM + KEY_DIM + hk * DK + dk];

    __shared__ float s1[128], s2[128];
    s1[dk] = qv * qv;
    s2[dk] = kv * kv;
    __syncthreads();
#pragma unroll
    for (int off = 64; off > 0; off >>= 1) {
        if (dk < off) { s1[dk] += s1[dk + off]; s2[dk] += s2[dk + off]; }
        __syncthreads();
    }
    __shared__ float rq, rk;
    if (dk == 0) {
        rq = rsqrtf(s1[0] + 1e-6f);
        rk = rsqrtf(s2[0] + 1e-6f);
    }
    __syncthreads();

    float qo = qv * rq * 0.08838834764831845f;
    float ko = kv * rk;
    int h0 = hk * 2;
    size_t base0 = ((size_t)t * HV + h0) * DK + dk;
    size_t base1 = ((size_t)t * HV + h0 + 1) * DK + dk;
    qn[base0] = qo; qn[base1] = qo;
    kn[base0] = ko; kn[base1] = ko;
}

// ---------------------------------------------------------------------------
// Gated delta-rule recurrence, 128 CTAs (2 per chain, dv-halved), smem-reduce.
// Time-chunked: [s_begin, s_end) with exact fp32 state carry via g_state.
// ---------------------------------------------------------------------------
__global__ __launch_bounds__(128) void recurrence(
    const float* __restrict__ qn, const float* __restrict__ kn,
    const float* __restrict__ mixed, const float* __restrict__ gg,
    const float* __restrict__ bb, float* __restrict__ core,
    float* __restrict__ state, int s_begin, int s_end,
    int load_st, int store_st)
{
    const int cid   = blockIdx.x;          // 0..127
    const int chain = cid >> 1;            // b*HV + h
    const int dvh   = (cid & 1) * 64;
    const int b = chain / HV, h = chain % HV;
    const int tid = threadIdx.x;
    const int dvl = tid & 63;
    const int dkh = (tid >> 6) * 64;
    const int dv  = dvh + dvl;
    const size_t stbase = (size_t)chain * (DK * DV);

    float st[64];
    if (load_st) {
#pragma unroll
        for (int i = 0; i < 64; i++)
            st[i] = state[stbase + (size_t)(dkh + i) * DV + dv];
    } else {
#pragma unroll
        for (int i = 0; i < 64; i++) st[i] = 0.f;
    }

    __shared__ float ks[2][DK], qs[2][DK], red1[128], red2[128];

    const int t0 = b * SS + s_begin;
    ks[s_begin & 1][tid] = kn[((size_t)t0 * HV + h) * DK + tid];
    qs[s_begin & 1][tid] = qn[((size_t)t0 * HV + h) * DK + tid];
    float gv = gg[t0 * HV + h];
    float bv = bb[t0 * HV + h];
    float vv = mixed[(size_t)t0 * CONV_DIM + 2 * KEY_DIM + h * DV + dv];
    __syncthreads();

    for (int s = s_begin; s < s_end; s++) {
        const int cur = s & 1;
        const int t = b * SS + s;

        float knx = 0.f, qnx = 0.f, gnx = 0.f, bnx = 0.f, vnx = 0.f;
        if (s + 1 < s_end) {
            int tn = t + 1;
            knx = kn[((size_t)tn * HV + h) * DK + tid];
            qnx = qn[((size_t)tn * HV + h) * DK + tid];
            gnx = gg[tn * HV + h];
            bnx = bb[tn * HV + h];
            vnx = mixed[(size_t)tn * CONV_DIM + 2 * KEY_DIM + h * DV + dv];
        }

        const float dec = expf(gv);

        float m0 = 0.f, m1 = 0.f, m2 = 0.f, m3 = 0.f;
#pragma unroll
        for (int i = 0; i < 64; i += 4) {
            float4 kk = *reinterpret_cast<const float4*>(&ks[cur][dkh + i]);
            st[i + 0] *= dec; m0 += kk.x * st[i + 0];
            st[i + 1] *= dec; m1 += kk.y * st[i + 1];
            st[i + 2] *= dec; m2 += kk.z * st[i + 2];
            st[i + 3] *= dec; m3 += kk.w * st[i + 3];
        }
        red1[tid] = (m0 + m1) + (m2 + m3);
        __syncthreads();
        const float mem = red1[tid] + red1[tid ^ 64];
        const float delta = (vv - mem) * bv;

        float o0 = 0.f, o1 = 0.f, o2 = 0.f, o3 = 0.f;
#pragma unroll
        for (int i = 0; i < 64; i += 4) {
            float4 kk = *reinterpret_cast<const float4*>(&ks[cur][dkh + i]);
            float4 qq = *reinterpret_cast<const float4*>(&qs[cur][dkh + i]);
            st[i + 0] += kk.x * delta; o0 += qq.x * st[i + 0];
            st[i + 1] += kk.y * delta; o1 += qq.y * st[i + 1];
            st[i + 2] += kk.z * delta; o2 += qq.z * st[i + 2];
            st[i + 3] += kk.w * delta; o3 += qq.w * st[i + 3];
        }
        red2[tid] = (o0 + o1) + (o2 + o3);

        if (s + 1 < s_end) {
            ks[cur ^ 1][tid] = knx;
            qs[cur ^ 1][tid] = qnx;
        }
        __syncthreads();
        if (dkh == 0)
            core[((size_t)t * HV + h) * DV + dv] = red2[tid] + red2[tid ^ 64];

        gv = gnx; bv = bnx; vv = vnx;
    }

    if (store_st) {
#pragma unroll
        for (int i = 0; i < 64; i++)
            state[stbase + (size_t)(dkh + i) * DV + dv] = st[i];
    }
}

// ---------------------------------------------------------------------------
// gated RMSNorm -> fp16 hi/lo; t_off selects the token slice
// ---------------------------------------------------------------------------
__global__ __launch_bounds__(128) void gated_norm(
    const float* __restrict__ core, const float* __restrict__ z,
    const float* __restrict__ nw, __half* __restrict__ nh,
    __half* __restrict__ nl, int t_off)
{
    int bh = blockIdx.x + t_off * HV;
    int dv = threadIdx.x;
    size_t idx = (size_t)bh * DV + dv;

    float c  = core[idx];
    float zv = z[idx];
    float gz = c * (zv / (1.f + expf(-zv)));

    __shared__ float red[128];
    red[dv] = gz * gz;
    __syncthreads();
#pragma unroll
    for (int off = 64; off > 0; off >>= 1) {
        if (dv < off) red[dv] += red[dv + off];
        __syncthreads();
    }
    __shared__ float rs;
    if (dv == 0) rs = rsqrtf(red[0] * (1.f / DV) + 1e-6f);
    __syncthreads();

    __half h, l;
    hsplit(gz * rs * nw[dv], h, l);
    nh[idx] = h; nl[idx] = l;
}

// ---------------------------------------------------------------------------
// launch — 3-stream pipelined overlap (graph-capturable event fork/join)
// ---------------------------------------------------------------------------
extern "C" void kernel_launch(void* const* d_in, const int* in_sizes, int n_in,
                              void* d_out, int out_size)
{
    const float* x       = (const float*)d_in[0];
    const float* Wqkv    = (const float*)d_in[1];
    const float* Wz      = (const float*)d_in[2];
    const float* Wb      = (const float*)d_in[3];
    const float* Wa      = (const float*)d_in[4];
    const float* conv_w  = (const float*)d_in[5];
    const float* conv_b  = (const float*)d_in[6];
    const float* dt_bias = (const float*)d_in[7];
    const float* A_log   = (const float*)d_in[8];
    const float* norm_w  = (const float*)d_in[9];
    const float* Wout    = (const float*)d_in[10];
    float* out = (float*)d_out;

    float *qkv_pre, *mixed, *z, *qn, *kn, *gbuf, *bbuf, *core, *state;
    __half *xh, *xl, *WqT, *WzT, *WoT, *nh, *nl;
    cudaGetSymbolAddress((void**)&qkv_pre, g_qkv_pre);
    cudaGetSymbolAddress((void**)&mixed,   g_mixed);
    cudaGetSymbolAddress((void**)&z,       g_z);
    cudaGetSymbolAddress((void**)&qn,      g_qn);
    cudaGetSymbolAddress((void**)&kn,      g_kn);
    cudaGetSymbolAddress((void**)&gbuf,    g_g);
    cudaGetSymbolAddress((void**)&bbuf,    g_beta);
    cudaGetSymbolAddress((void**)&core,    g_core);
    cudaGetSymbolAddress((void**)&state,   g_state);
    cudaGetSymbolAddress((void**)&xh,      g_xh);
    cudaGetSymbolAddress((void**)&xl,      g_xl);
    cudaGetSymbolAddress((void**)&WqT,     g_WqkvT);
    cudaGetSymbolAddress((void**)&WzT,     g_WzT);
    cudaGetSymbolAddress((void**)&WoT,     g_WoutT);
    cudaGetSymbolAddress((void**)&nh,      g_nrm_h);
    cudaGetSymbolAddress((void**)&nl,      g_nrm_l);

    static cudaStream_t s1 = nullptr, s2 = nullptr;
    static cudaEvent_t ev_root, ev_prep, ev_qkv, ev_z0, ev_z1, ev_rec0, ev_out1;
    if (!s1) {
        cudaStreamCreateWithFlags(&s1, cudaStreamNonBlocking);
        cudaStreamCreateWithFlags(&s2, cudaStreamNonBlocking);
        cudaEventCreateWithFlags(&ev_root, cudaEventDisableTiming);
        cudaEventCreateWithFlags(&ev_prep, cudaEventDisableTiming);
        cudaEventCreateWithFlags(&ev_qkv,  cudaEventDisableTiming);
        cudaEventCreateWithFlags(&ev_z0,   cudaEventDisableTiming);
        cudaEventCreateWithFlags(&ev_z1,   cudaEventDisableTiming);
        cudaEventCreateWithFlags(&ev_rec0, cudaEventDisableTiming);
        cudaEventCreateWithFlags(&ev_out1, cudaEventDisableTiming);
        cudaFuncSetAttribute(gemm_fp16_2t,
            cudaFuncAttributeMaxDynamicSharedMemorySize, GEMM_SMEM);
        cudaFuncSetAttribute(gemm_fp16_1t,
            cudaFuncAttributeMaxDynamicSharedMemorySize, GEMM1_SMEM);
    }

    // fork s1 off main
    cudaEventRecord(ev_root, 0);
    cudaStreamWaitEvent(s1, ev_root, 0);

    // main: x split + Wqkv convert -> qkv GEMM
    split_fp16<<<(TT * HH / 4 + 255) / 256, 256>>>(
        (const float4*)x, xh, xl, TT * HH / 4);
    cvt_fp16_T<<<dim3(CONV_DIM / 32, HH / 32), 256>>>(Wqkv, WqT, HH, CONV_DIM);

    // s1: Wz/Wout converts + proj_gb (overlap qkv GEMM)
    cvt_fp16_T<<<dim3(VAL_DIM / 32, HH / 32), 256, 0, s1>>>(Wz, WzT, HH, VAL_DIM);
    cvt_fp16_T<<<dim3(HH / 32, VAL_DIM / 32), 256, 0, s1>>>(Wout, WoT, VAL_DIM, HH);
    proj_gb<<<TT, 256, 0, s1>>>(x, Wb, Wa, dt_bias, A_log, gbuf, bbuf);
    cudaEventRecord(ev_prep, s1);

    // main: qkv GEMM (2-term)
    gemm_fp16_2t<<<dim3(CONV_DIM / 128, TT / 128), 256, GEMM_SMEM>>>(
        xh, xl, WqT, qkv_pre, TT, CONV_DIM, HH);
    cudaEventRecord(ev_qkv, 0);

    // s1: z GEMM (1-term) chunked by token rows
    cudaStreamWaitEvent(s1, ev_qkv, 0);
    gemm_fp16_1t<<<dim3(VAL_DIM / 128, SHALF / 128), 256, GEMM1_SMEM, s1>>>(
        xh, WzT, z, SHALF, VAL_DIM, HH);
    gemm_fp16_1t<<<dim3(VAL_DIM / 128, SHALF / 128), 256, GEMM1_SMEM, s1>>>(
        xh + (size_t)SS * HH, WzT, z + (size_t)SS * VAL_DIM, SHALF, VAL_DIM, HH);
    cudaEventRecord(ev_z0, s1);
    gemm_fp16_1t<<<dim3(VAL_DIM / 128, SHALF / 128), 256, GEMM1_SMEM, s1>>>(
        xh + (size_t)SHALF * HH, WzT, z + (size_t)SHALF * VAL_DIM,
        SHALF, VAL_DIM, HH);
    gemm_fp16_1t<<<dim3(VAL_DIM / 128, SHALF / 128), 256, GEMM1_SMEM, s1>>>(
        xh + (size_t)(SS + SHALF) * HH, WzT,
        z + (size_t)(SS + SHALF) * VAL_DIM, SHALF, VAL_DIM, HH);
    cudaEventRecord(ev_z1, s1);

    // main: conv + qk prep + rec chunk 0 (s in [0,512))
    conv_silu<<<dim3(CONV_DIM / 256, TT), 256>>>(qkv_pre, conv_w, conv_b, mixed);
    qk_prep<<<TT * HK, 128>>>(mixed, qn, kn);
    cudaStreamWaitEvent(0, ev_prep, 0);
    recurrence<<<BB * HV * 2, 128>>>(qn, kn, mixed, gbuf, bbuf, core,
                                     state, 0, SHALF, 0, 1);
    cudaEventRecord(ev_rec0, 0);

    // s2: norm + out-GEMM (2-term) for chunk-0 token slices
    cudaStreamWaitEvent(s2, ev_z0, 0);
    cudaStreamWaitEvent(s2, ev_rec0, 0);
    gated_norm<<<SHALF * HV, 128, 0, s2>>>(core, z, norm_w, nh, nl, 0);
    gated_norm<<<SHALF * HV, 128, 0, s2>>>(core, z, norm_w, nh, nl, SS);
    gemm_fp16_2t<<<dim3(HH / 128, SHALF / 128), 256, GEMM_SMEM, s2>>>(
        nh, nl, WoT, out, SHALF, HH, VAL_DIM);
    gemm_fp16_2t<<<dim3(HH / 128, SHALF / 128), 256, GEMM_SMEM, s2>>>(
        nh + (size_t)SS * VAL_DIM, nl + (size_t)SS * VAL_DIM, WoT,
        out + (size_t)SS * HH, SHALF, HH, VAL_DIM);
    cudaEventRecord(ev_out1, s2);

    // main: rec chunk 1, then norm+out for chunk-1 slices
    recurrence<<<BB * HV * 2, 128>>>(qn, kn, mixed, gbuf, bbuf, core,
                                     state, SHALF, SS, 1, 0);
    cudaStreamWaitEvent(0, ev_z1, 0);
    gated_norm<<<SHALF * HV, 128>>>(core, z, norm_w, nh, nl, SHALF);
    gated_norm<<<SHALF * HV, 128>>>(core, z, norm_w, nh, nl, SS + SHALF);
    gemm_fp16_2t<<<dim3(HH / 128, SHALF / 128), 256, GEMM_SMEM>>>(
        nh + (size_t)SHALF * VAL_DIM, nl + (size_t)SHALF * VAL_DIM,
        WoT, out + (size_t)SHALF * HH, SHALF, HH, VAL_DIM);
    gemm_fp16_2t<<<dim3(HH / 128, SHALF / 128), 256, GEMM_SMEM>>>(
        nh + (size_t)(SS + SHALF) * VAL_DIM, nl + (size_t)(SS + SHALF) * VAL_DIM,
        WoT, out + (size_t)(SS + SHALF) * HH, SHALF, HH, VAL_DIM);

    // join s2 back into main before capture ends
    cudaStreamWaitEvent(0, ev_out1, 0);
}